// round 3
// baseline (speedup 1.0000x reference)
#include <cuda_runtime.h>

#define NB   256
#define NPTS 2000
#define M1   100
#define M2   5
#define K1   20
#define K2   20
#define F1   5
#define F2   25
#define F3   45
#define NT   512
#define NWARP (NT/32)

__device__ __forceinline__ void argmax_xor(float& v, int& i){
  #pragma unroll
  for (int off = 16; off; off >>= 1){
    float ov = __shfl_xor_sync(0xffffffffu, v, off);
    int   oi = __shfl_xor_sync(0xffffffffu, i, off);
    if (ov > v || (ov == v && oi < i)) { v = ov; i = oi; }
  }
}

__device__ __forceinline__ float fmin_xor(float v){
  #pragma unroll
  for (int off = 16; off; off >>= 1)
    v = fminf(v, __shfl_xor_sync(0xffffffffu, v, off));
  return v;
}

__device__ __forceinline__ int isum_xor(int v){
  #pragma unroll
  for (int off = 16; off; off >>= 1)
    v += __shfl_xor_sync(0xffffffffu, v, off);
  return v;
}

__global__ void __launch_bounds__(NT)
net_kernel(const float* __restrict__ points,
           const float* __restrict__ W1, const float* __restrict__ b1,
           const float* __restrict__ W2, const float* __restrict__ b2,
           const float* __restrict__ W3, const float* __restrict__ b3,
           const float* __restrict__ D1, const float* __restrict__ bD1,
           const float* __restrict__ D2, const float* __restrict__ bD2,
           const float* __restrict__ D3, const float* __restrict__ bD3,
           float* __restrict__ out)
{
  __shared__ float s_px[NPTS], s_py[NPTS], s_pz[NPTS];
  __shared__ float s_mind[NPTS];
  __shared__ float s_sx[M1], s_sy[M1], s_sz[M1];
  __shared__ float s_f1[M1][F1];
  __shared__ float s_f2[M2][F2];
  __shared__ float s_s2x[M2], s_s2y[M2], s_s2z[M2];
  __shared__ int   s_s2i[M2];
  __shared__ float s_latent[F3];
  __shared__ float s_o1[140];
  __shared__ float s_cf[125];
  __shared__ float s_o2[800];
  __shared__ float s_W1[15], s_b1[F1];
  __shared__ float s_W2[200], s_b2[F2];
  __shared__ float s_redv[NWARP];
  __shared__ int   s_redi[NWARP];
  __shared__ int   s_last;

  const int b = blockIdx.x, tid = threadIdx.x;
  const int lane = tid & 31, wid = tid >> 5;
  const float* P = points + (size_t)b * NPTS * 3;

  // ---- Stage 0: load cloud + small weights into shared ----
  for (int i = tid; i < NPTS; i += NT){
    s_px[i] = P[3*i+0];
    s_py[i] = P[3*i+1];
    s_pz[i] = P[3*i+2];
    s_mind[i] = 1e10f;
  }
  if (tid < 15)  s_W1[tid] = W1[tid];
  if (tid < F1)  s_b1[tid] = b1[tid];
  if (tid >= 32 && tid < 232)       s_W2[tid-32]  = W2[tid-32];
  if (tid >= 256 && tid < 256+F2)   s_b2[tid-256] = b2[tid-256];
  __syncthreads();

  // ---- Stage 1: FPS level 1 (2000 -> 100) ----
  // Reference semantics: idx[s] = last (before update); mind=min(mind,d2(last));
  // last = argmax(mind) with first-occurrence (smallest-index) tie break.
  {
    int last = 0;
    for (int s = 0; s < M1; s++){
      if (tid == 0){ s_sx[s] = s_px[last]; s_sy[s] = s_py[last]; s_sz[s] = s_pz[last]; }
      const float lx = s_px[last], ly = s_py[last], lz = s_pz[last];
      float bv = -1.0f; int bi = 0;
      for (int i = tid; i < NPTS; i += NT){
        float dx = s_px[i]-lx, dy = s_py[i]-ly, dz = s_pz[i]-lz;
        float d  = dx*dx + dy*dy + dz*dz;
        float m  = s_mind[i];
        m = d < m ? d : m;
        s_mind[i] = m;
        if (m > bv){ bv = m; bi = i; }   // ascending i => keeps smallest index on tie
      }
      argmax_xor(bv, bi);
      if (lane == 0){ s_redv[wid] = bv; s_redi[wid] = bi; }
      __syncthreads();
      if (wid == 0){
        float v  = (lane < NWARP) ? s_redv[lane] : -2.0f;
        int   i2 = (lane < NWARP) ? s_redi[lane] : 0;
        argmax_xor(v, i2);
        if (lane == 0) s_last = i2;
      }
      __syncthreads();
      last = s_last;
    }
  }

  // ---- Stage 2: radius-kNN level 1 + f1 (one warp per query) ----
  {
    const float r1sq = 0.09f;          // R1*R1
    const float inv_r1 = 1.0f / 0.3f;
    for (int q = wid; q < M1; q += NWARP){
      const float sx = s_sx[q], sy = s_sy[q], sz = s_sz[q];
      int cnt = 0;
      for (int i = lane; i < NPTS; i += 32){
        float dx = s_px[i]-sx, dy = s_py[i]-sy, dz = s_pz[i]-sz;
        float d  = dx*dx + dy*dy + dz*dz;
        cnt += (d <= r1sq);
      }
      cnt = isum_xor(cnt);
      float t = r1sq;
      if (cnt > K1){
        // rare: find K1-th smallest distance by iterated warp-min
        float prev = -1.0f;
        for (int k = 0; k < K1; k++){
          float mn = 3.0e38f;
          for (int i = lane; i < NPTS; i += 32){
            float dx = s_px[i]-sx, dy = s_py[i]-sy, dz = s_pz[i]-sz;
            float d  = dx*dx + dy*dy + dz*dz;
            if (d > prev && d < mn) mn = d;
          }
          prev = fmin_xor(mn);
        }
        t = prev;
      }
      float f[F1];
      #pragma unroll
      for (int j = 0; j < F1; j++) f[j] = -1e10f;
      for (int i = lane; i < NPTS; i += 32){
        float dx = s_px[i]-sx, dy = s_py[i]-sy, dz = s_pz[i]-sz;
        float d  = dx*dx + dy*dy + dz*dz;
        if (d <= t){
          float rx = dx*inv_r1, ry = dy*inv_r1, rz = dz*inv_r1;
          #pragma unroll
          for (int j = 0; j < F1; j++){
            float h = rx*s_W1[j] + ry*s_W1[F1+j] + rz*s_W1[2*F1+j] + s_b1[j];
            h = h > 0.0f ? h : 0.0f;
            f[j] = fmaxf(f[j], h);
          }
        }
      }
      #pragma unroll
      for (int j = 0; j < F1; j++){
        #pragma unroll
        for (int off = 16; off; off >>= 1)
          f[j] = fmaxf(f[j], __shfl_xor_sync(0xffffffffu, f[j], off));
      }
      if (lane == 0){
        #pragma unroll
        for (int j = 0; j < F1; j++) s_f1[q][j] = f[j];
      }
    }
  }
  __syncthreads();

  // ---- Stage 3: FPS level 2 (100 -> 5), single warp ----
  if (wid == 0){
    float m[4];
    #pragma unroll
    for (int u = 0; u < 4; u++) m[u] = 1e10f;
    int last2 = 0;
    for (int s = 0; s < M2; s++){
      if (lane == 0) s_s2i[s] = last2;
      const float lx = s_sx[last2], ly = s_sy[last2], lz = s_sz[last2];
      float bv = -1.0f; int bi = 0;
      #pragma unroll
      for (int u = 0; u < 4; u++){
        int i = lane + 32*u;
        if (i < M1){
          float dx = s_sx[i]-lx, dy = s_sy[i]-ly, dz = s_sz[i]-lz;
          float d  = dx*dx + dy*dy + dz*dz;
          if (d < m[u]) m[u] = d;
          if (m[u] > bv){ bv = m[u]; bi = i; }
        }
      }
      argmax_xor(bv, bi);
      last2 = __shfl_sync(0xffffffffu, bi, 0);
    }
  }
  __syncthreads();
  if (tid < M2){
    int i = s_s2i[tid];
    s_s2x[tid] = s_sx[i]; s_s2y[tid] = s_sy[i]; s_s2z[tid] = s_sz[i];
  }
  __syncthreads();

  // ---- Stage 4: radius-kNN level 2 + f2 (warps 0..4, one per query) ----
  if (wid < M2){
    const int q = wid;
    const float r2sq = 1.0f;
    const float sx = s_s2x[q], sy = s_s2y[q], sz = s_s2z[q];
    int cnt = 0;
    for (int i = lane; i < M1; i += 32){
      float dx = s_sx[i]-sx, dy = s_sy[i]-sy, dz = s_sz[i]-sz;
      float d  = dx*dx + dy*dy + dz*dz;
      cnt += (d <= r2sq);
    }
    cnt = isum_xor(cnt);
    float t = r2sq;
    if (cnt > K2){
      float prev = -1.0f;
      for (int k = 0; k < K2; k++){
        float mn = 3.0e38f;
        for (int i = lane; i < M1; i += 32){
          float dx = s_sx[i]-sx, dy = s_sy[i]-sy, dz = s_sz[i]-sz;
          float d  = dx*dx + dy*dy + dz*dz;
          if (d > prev && d < mn) mn = d;
        }
        prev = fmin_xor(mn);
      }
      t = prev;
    }
    float f[F2];
    #pragma unroll
    for (int j = 0; j < F2; j++) f[j] = -1e10f;
    for (int i = lane; i < M1; i += 32){
      float dx = s_sx[i]-sx, dy = s_sy[i]-sy, dz = s_sz[i]-sz;
      float d  = dx*dx + dy*dy + dz*dz;
      if (d <= t){
        float in0 = dx, in1 = dy, in2 = dz;   // R2 = 1.0
        float g0 = s_f1[i][0], g1 = s_f1[i][1], g2 = s_f1[i][2],
              g3 = s_f1[i][3], g4 = s_f1[i][4];
        #pragma unroll
        for (int j = 0; j < F2; j++){
          float h = s_b2[j]
                  + in0*s_W2[0*F2+j] + in1*s_W2[1*F2+j] + in2*s_W2[2*F2+j]
                  + g0*s_W2[3*F2+j] + g1*s_W2[4*F2+j] + g2*s_W2[5*F2+j]
                  + g3*s_W2[6*F2+j] + g4*s_W2[7*F2+j];
          h = h > 0.0f ? h : 0.0f;
          f[j] = fmaxf(f[j], h);
        }
      }
    }
    #pragma unroll
    for (int j = 0; j < F2; j++){
      #pragma unroll
      for (int off = 16; off; off >>= 1)
        f[j] = fmaxf(f[j], __shfl_xor_sync(0xffffffffu, f[j], off));
    }
    if (lane == 0){
      #pragma unroll
      for (int j = 0; j < F2; j++) s_f2[q][j] = f[j];
    }
  }
  __syncthreads();

  // ---- Stage 5: h3 + latent (45 threads) ----
  if (tid < F3){
    float mx = -3.0e38f;
    for (int i = 0; i < M2; i++){
      float h = b3[tid];
      h += (s_s2x[i]*0.5f) * W3[0*F3+tid];
      h += (s_s2y[i]*0.5f) * W3[1*F3+tid];
      h += (s_s2z[i]*0.5f) * W3[2*F3+tid];
      #pragma unroll 5
      for (int c = 0; c < F2; c++)
        h += s_f2[i][c] * W3[(3+c)*F3+tid];
      h = h > 0.0f ? h : 0.0f;
      mx = fmaxf(mx, h);
    }
    s_latent[tid] = mx;
  }
  __syncthreads();

  // ---- Stage 6: o1 = latent @ D1 + bD1 (140 outputs) ----
  if (tid < 140){
    float v = bD1[tid];
    #pragma unroll 5
    for (int i = 0; i < F3; i++)
      v += s_latent[i] * D1[i*140 + tid];
    s_o1[tid] = v;
  }
  __syncthreads();
  if (tid < 125){
    int i = tid / F2, c = tid % F2;
    float v = s_o1[i*28 + 3 + c];
    s_cf[tid] = v > 0.0f ? v : 0.0f;
  }
  __syncthreads();

  // ---- Stage 7: o2 = cf @ D2 + bD2 (5x160 = 800 outputs) ----
  for (int t = tid; t < 800; t += NT){
    int i = t / 160, j = t % 160;
    float v = bD2[j];
    #pragma unroll 5
    for (int c = 0; c < F2; c++)
      v += s_cf[i*F2 + c] * D2[c*160 + j];
    s_o2[t] = v;
  }
  __syncthreads();

  // ---- Stage 8: dec3 + folding combine, write 2000x3 outputs ----
  {
    float* O = out + (size_t)b * NPTS * 3;
    for (int t = tid; t < NPTS*3; t += NT){
      int g   = t / 3;
      int c   = t - 3*g;
      int i2  = g / 400;     // level-2 row (0..4)
      int r1  = g / 20;      // level-1 row (0..99)
      int j20 = g % 20;      // dec3 column group
      int j8  = r1 % 20;
      float dec  = s_o1[i2*28 + c];
      float dec2 = s_o2[i2*160 + j8*8 + c];
      float acc  = bD3[j20*3 + c];
      #pragma unroll
      for (int f = 0; f < F1; f++){
        float cf2 = s_o2[i2*160 + j8*8 + 3 + f];
        cf2 = cf2 > 0.0f ? cf2 : 0.0f;
        acc += cf2 * D3[f*60 + j20*3 + c];
      }
      O[t] = ((dec*2.0f + dec2)*1.0f + acc) * 0.3f;
    }
  }
}

extern "C" void kernel_launch(void* const* d_in, const int* in_sizes, int n_in,
                              void* d_out, int out_size)
{
  net_kernel<<<NB, NT>>>(
      (const float*)d_in[0],
      (const float*)d_in[1],  (const float*)d_in[2],
      (const float*)d_in[3],  (const float*)d_in[4],
      (const float*)d_in[5],  (const float*)d_in[6],
      (const float*)d_in[7],  (const float*)d_in[8],
      (const float*)d_in[9],  (const float*)d_in[10],
      (const float*)d_in[11], (const float*)d_in[12],
      (float*)d_out);
}